// round 6
// baseline (speedup 1.0000x reference)
#include <cuda_runtime.h>
#include <math.h>

#define NB 2
#define NW 16
#define NN 1000
#define NT 16000       // NW*NN
#define FIN 16
#define ESP 16000      // spatial edges
#define DE 8
#define HID 128
#define NLAYER 3

// ---------------- scratch (device globals; no cudaMalloc allowed) ----------------
__device__ float g_x[NB * NT * HID];          // 16.4 MB
__device__ float g_qkv[NB * NT * 3 * HID];    // 49 MB   layout (row, 384): Q|K|V
__device__ float g_msg[NB * NT * HID];        // 16.4 MB
__device__ float g_y[NB * NT * HID];          // 16.4 MB
__device__ float g_film[(ESP + 1) * 2 * HID]; // 16.4 MB (gamma|beta per distinct edge-attr)
__device__ float g_meanea[DE];
__device__ int   g_hist[NN];
__device__ int   g_indptr[NN + 1];
__device__ int   g_cursor[NN];
__device__ int   g_spedge[ESP];

// ---------------- CSR build over the 1000 spatial dst nodes ----------------
__global__ void k_zero() {
    int t = blockIdx.x * blockDim.x + threadIdx.x;
    if (t < NN) g_hist[t] = 0;
}

__global__ void k_hist(const int* __restrict__ ei) {
    int j = blockIdx.x * blockDim.x + threadIdx.x;
    if (j < ESP) atomicAdd(&g_hist[ei[ESP + j]], 1);
}

__global__ void k_scan() {   // 1 block, 1024 threads
    __shared__ int sh[1024];
    int t = threadIdx.x;
    int v = (t < NN) ? g_hist[t] : 0;
    sh[t] = v;
    __syncthreads();
    for (int off = 1; off < 1024; off <<= 1) {
        int u = (t >= off) ? sh[t - off] : 0;
        __syncthreads();
        sh[t] += u;
        __syncthreads();
    }
    if (t < NN) { g_indptr[t + 1] = sh[t]; g_cursor[t] = sh[t] - v; }
    if (t == 0) g_indptr[0] = 0;
}

__global__ void k_fill(const int* __restrict__ ei) {
    int j = blockIdx.x * blockDim.x + threadIdx.x;
    if (j < ESP) {
        int d = ei[ESP + j];
        int p = atomicAdd(&g_cursor[d], 1);
        g_spedge[p] = j;
    }
}

// ---------------- mean of spatial edge attrs (for temporal edges) ----------------
__global__ void k_meanea(const float* __restrict__ ea) {  // grid = DE blocks
    __shared__ float sh[256];
    int t = threadIdx.x, c = blockIdx.x;
    float s = 0.f;
    for (int r = t; r < ESP; r += 256) s += ea[r * DE + c];
    sh[t] = s;
    __syncthreads();
    for (int off = 128; off; off >>= 1) {
        if (t < off) sh[t] += sh[t + off];
        __syncthreads();
    }
    if (t == 0) g_meanea[c] = sh[0] / (float)ESP;
}

// ---------------- input projection (B*NT, 16) @ (16,128) ----------------
__global__ void __launch_bounds__(128) k_inproj(const float* __restrict__ xw,
                                                const float* __restrict__ w,
                                                const float* __restrict__ b) {
    __shared__ float a[8][FIN];
    int t = threadIdx.x;
    int r0 = blockIdx.x * 8;
    a[t / 16][t % 16] = xw[(size_t)(r0 + t / 16) * FIN + (t % 16)];
    __syncthreads();
    float wk[FIN];
#pragma unroll
    for (int k = 0; k < FIN; k++) wk[k] = w[k * HID + t];
    float bb = b[t];
#pragma unroll
    for (int rr = 0; rr < 8; rr++) {
        float s = bb;
#pragma unroll
        for (int k = 0; k < FIN; k++) s += a[rr][k] * wk[k];
        g_x[(size_t)(r0 + rr) * HID + t] = s;
    }
}

// ---------------- FiLM: (16001, 8) @ (8, 256) ----------------
__global__ void __launch_bounds__(256) k_film(const float* __restrict__ ea,
                                              const float* __restrict__ fw,
                                              const float* __restrict__ fb) {
    __shared__ float at[DE];
    int j = blockIdx.x, c = threadIdx.x;
    if (c < DE) at[c] = (j < ESP) ? ea[j * DE + c] : g_meanea[c];
    __syncthreads();
    float s = fb[c];
#pragma unroll
    for (int k = 0; k < DE; k++) s += at[k] * fw[k * 256 + c];
    g_film[(size_t)j * 256 + c] = s;
}

// ---------------- tiled fp32 GEMM: C[M,128] = A[M,128] @ W[128,128] + bias ----------------
// BM=64, BN=64, BK=16, 256 threads, 4x4 per thread.
// mode 0 (QKV): grid (M/64, 2, 3). A = g_x, C = g_qkv (ldc 384), weight z of {qw,kw,vw},
//               column offset z*128.
// mode 1 (O):   grid (M/64, 2, 1). A = g_msg, C = g_y (ldc 128), weight W0.
// NOTE: scratch buffers are selected INSIDE device code — passing __device__
// globals as host-side kernel args yields the host shadow symbol (the round-1
// bug: ATS made it silently "work" against host memory).
__global__ void __launch_bounds__(256) k_gemm(int mode,
                                              const float* __restrict__ W0,
                                              const float* __restrict__ W1,
                                              const float* __restrict__ W2,
                                              const float* __restrict__ b0,
                                              const float* __restrict__ b1,
                                              const float* __restrict__ b2,
                                              int ldc) {
    const float* __restrict__ A = (mode == 0) ? g_x : g_msg;
    float* __restrict__ C = (mode == 0) ? g_qkv : g_y;
    int z = blockIdx.z;
    const float* __restrict__ W = (z == 0) ? W0 : (z == 1) ? W1 : W2;
    const float* __restrict__ bias = (z == 0) ? b0 : (z == 1) ? b1 : b2;
    int cOff = z * HID;

    __shared__ float As[16][68];
    __shared__ float Bs[16][64];
    int tid = threadIdx.x;
    int r0 = blockIdx.x * 64;
    int c0 = blockIdx.y * 64;
    int tx = tid & 15, ty = tid >> 4;
    int arow = tid >> 2, acol = (tid & 3) << 2;
    int brow = tid >> 4, bcol = (tid & 15) << 2;
    float acc[4][4] = {};
    for (int k0 = 0; k0 < 128; k0 += 16) {
        float4 a = *(const float4*)(A + (size_t)(r0 + arow) * 128 + k0 + acol);
        As[acol + 0][arow] = a.x;
        As[acol + 1][arow] = a.y;
        As[acol + 2][arow] = a.z;
        As[acol + 3][arow] = a.w;
        *(float4*)(&Bs[brow][bcol]) =
            *(const float4*)(W + (size_t)(k0 + brow) * 128 + c0 + bcol);
        __syncthreads();
#pragma unroll
        for (int k = 0; k < 16; k++) {
            float4 av = *(const float4*)(&As[k][ty << 2]);
            float4 bv = *(const float4*)(&Bs[k][tx << 2]);
            acc[0][0] += av.x * bv.x; acc[0][1] += av.x * bv.y;
            acc[0][2] += av.x * bv.z; acc[0][3] += av.x * bv.w;
            acc[1][0] += av.y * bv.x; acc[1][1] += av.y * bv.y;
            acc[1][2] += av.y * bv.z; acc[1][3] += av.y * bv.w;
            acc[2][0] += av.z * bv.x; acc[2][1] += av.z * bv.y;
            acc[2][2] += av.z * bv.z; acc[2][3] += av.z * bv.w;
            acc[3][0] += av.w * bv.x; acc[3][1] += av.w * bv.y;
            acc[3][2] += av.w * bv.z; acc[3][3] += av.w * bv.w;
        }
        __syncthreads();
    }
#pragma unroll
    for (int i = 0; i < 4; i++) {
        size_t r = r0 + (ty << 2) + i;
#pragma unroll
        for (int j = 0; j < 4; j++) {
            int c = c0 + (tx << 2) + j;
            C[r * ldc + cOff + c] = acc[i][j] + bias[c];
        }
    }
}

// ---------------- graph attention: warp per (batch, node), online softmax ----------------
__global__ void __launch_bounds__(256) k_attn(const int* __restrict__ ei) {
    int gwarp = (blockIdx.x * blockDim.x + threadIdx.x) >> 5;
    if (gwarp >= NB * NT) return;
    int lane = threadIdx.x & 31;
    int b = gwarp / NT, n = gwarp - b * NT;
    int w = n / NN, d = n - w * NN;

    const float* qrow = g_qkv + ((size_t)(b * NT + n)) * 384;
    float4 q = *(const float4*)(qrow + lane * 4);

    float m = -INFINITY, s = 0.f;
    float4 acc = make_float4(0.f, 0.f, 0.f, 0.f);

    int beg = g_indptr[d], end = g_indptr[d + 1];
    int nsp = end - beg;
    int nEdges = nsp + (w > 0 ? 1 : 0);

    for (int i = 0; i < nEdges; i++) {
        int src, fidx;
        if (i < nsp) {
            int j = g_spedge[beg + i];
            src = ei[j] + w * NN;   // ei[0] row = src
            fidx = j;
        } else {
            src = n - NN;
            fidx = ESP;
        }
        const float* krow = g_qkv + ((size_t)(b * NT + src)) * 384 + 128;
        float4 k = *(const float4*)(krow + lane * 4);
        float4 v = *(const float4*)(krow + 128 + lane * 4);
        const float* f = g_film + (size_t)fidx * 256 + lane * 4;
        float4 ga = *(const float4*)f;
        float4 be = *(const float4*)(f + 128);

        float p = q.x * (k.x * (1.f + ga.x) + be.x)
                + q.y * (k.y * (1.f + ga.y) + be.y)
                + q.z * (k.z * (1.f + ga.z) + be.z)
                + q.w * (k.w * (1.f + ga.w) + be.w);
        // per-head (8 lanes = 32 dims) reduction
        p += __shfl_xor_sync(0xffffffffu, p, 4);
        p += __shfl_xor_sync(0xffffffffu, p, 2);
        p += __shfl_xor_sync(0xffffffffu, p, 1);
        float logit = p * 0.1767766952966369f;  // 1/sqrt(32)

        float mn = fmaxf(m, logit);
        float sc = __expf(m - mn);   // 0 when m = -inf
        float wt = __expf(logit - mn);
        s = s * sc + wt;
        acc.x = acc.x * sc + wt * v.x;
        acc.y = acc.y * sc + wt * v.y;
        acc.z = acc.z * sc + wt * v.z;
        acc.w = acc.w * sc + wt * v.w;
        m = mn;
    }
    float inv = 1.f / (s + 1e-16f);
    float4 o = make_float4(acc.x * inv, acc.y * inv, acc.z * inv, acc.w * inv);
    *(float4*)(g_msg + ((size_t)(b * NT + n)) * HID + lane * 4) = o;
}

// ---------------- residual + layernorm, in-place on g_x ----------------
__global__ void __launch_bounds__(128) k_ln(const float* __restrict__ gamma,
                                            const float* __restrict__ beta) {
    int row = blockIdx.x, t = threadIdx.x;
    size_t idx = (size_t)row * HID + t;
    float v = g_x[idx] + g_y[idx];
    float a = v, q = v * v;
#pragma unroll
    for (int off = 16; off; off >>= 1) {
        a += __shfl_xor_sync(0xffffffffu, a, off);
        q += __shfl_xor_sync(0xffffffffu, q, off);
    }
    __shared__ float s1[4], s2[4];
    int wid = t >> 5;
    if ((t & 31) == 0) { s1[wid] = a; s2[wid] = q; }
    __syncthreads();
    float ta = s1[0] + s1[1] + s1[2] + s1[3];
    float tq = s2[0] + s2[1] + s2[2] + s2[3];
    float mu = ta * (1.f / HID);
    float var = tq * (1.f / HID) - mu * mu;
    g_x[idx] = (v - mu) * rsqrtf(var + 1e-5f) * gamma[t] + beta[t];
}

// ---------------- head: last window, dot-128 + softplus ----------------
__global__ void __launch_bounds__(128) k_head(const float* __restrict__ hw,
                                              const float* __restrict__ hb,
                                              float* __restrict__ out) {
    int gwarp = (blockIdx.x * blockDim.x + threadIdx.x) >> 5;
    if (gwarp >= NB * NN) return;
    int lane = threadIdx.x & 31;
    int b = gwarp / NN, n = gwarp - b * NN;
    const float* xr = g_x + ((size_t)(b * NT + (NW - 1) * NN + n)) * HID;
    float4 xv = *(const float4*)(xr + lane * 4);
    float4 wv = *(const float4*)(hw + lane * 4);
    float p = xv.x * wv.x + xv.y * wv.y + xv.z * wv.z + xv.w * wv.w;
#pragma unroll
    for (int off = 16; off; off >>= 1) p += __shfl_xor_sync(0xffffffffu, p, off);
    if (lane == 0) {
        float z = p + hb[0];
        out[gwarp] = fmaxf(z, 0.f) + log1pf(__expf(-fabsf(z)));
    }
}

// ---------------- launch ----------------
extern "C" void kernel_launch(void* const* d_in, const int* in_sizes, int n_in,
                              void* d_out, int out_size) {
    const float* xw  = (const float*)d_in[0];
    const int*   ei  = (const int*)d_in[1];
    const float* ea  = (const float*)d_in[2];
    const float* inw = (const float*)d_in[3];
    const float* inb = (const float*)d_in[4];
    const float* qw  = (const float*)d_in[5];
    const float* qb  = (const float*)d_in[6];
    const float* kw  = (const float*)d_in[7];
    const float* kb  = (const float*)d_in[8];
    const float* vw  = (const float*)d_in[9];
    const float* vb  = (const float*)d_in[10];
    const float* fw  = (const float*)d_in[11];
    const float* fb  = (const float*)d_in[12];
    const float* ow  = (const float*)d_in[13];
    const float* ob  = (const float*)d_in[14];
    const float* lng = (const float*)d_in[15];
    const float* lnb = (const float*)d_in[16];
    const float* hw  = (const float*)d_in[17];
    const float* hb  = (const float*)d_in[18];
    float* out = (float*)d_out;

    // CSR over spatial dst + mean edge attr
    k_zero<<<(NN + 255) / 256, 256>>>();
    k_hist<<<(ESP + 255) / 256, 256>>>(ei);
    k_scan<<<1, 1024>>>();
    k_fill<<<(ESP + 255) / 256, 256>>>(ei);
    k_meanea<<<DE, 256>>>(ea);

    // input projection
    k_inproj<<<(NB * NT) / 8, 128>>>(xw, inw, inb);

    const int M = NB * NT;  // 32000
    dim3 gQKV(M / 64, 2, 3);
    dim3 gO(M / 64, 2, 1);

    for (int l = 0; l < NLAYER; l++) {
        k_film<<<ESP + 1, 256>>>(ea, fw + (size_t)l * DE * 256, fb + (size_t)l * 256);
        k_gemm<<<gQKV, 256>>>(0,
                              qw + (size_t)l * HID * HID,
                              kw + (size_t)l * HID * HID,
                              vw + (size_t)l * HID * HID,
                              qb + l * HID, kb + l * HID, vb + l * HID, 384);
        k_attn<<<(NB * NT) / 8, 256>>>(ei);
        k_gemm<<<gO, 256>>>(1,
                            ow + (size_t)l * HID * HID, ow, ow,
                            ob + l * HID, ob, ob, 128);
        k_ln<<<M, 128>>>(lng + l * HID, lnb + l * HID);
    }

    k_head<<<(NB * NN + 3) / 4, 128>>>(hw, hb, out);
}

// round 8
// speedup vs baseline: 1.1683x; 1.1683x over previous
#include <cuda_runtime.h>
#include <cuda_bf16.h>
#include <math.h>
#include <stdint.h>

#define NB 2
#define NW 16
#define NN 1000
#define NT 16000       // NW*NN
#define FIN 16
#define ESP 16000      // spatial edges
#define DE 8
#define HID 128
#define NLAYER 3

// ---------------- scratch (device globals; no cudaMalloc allowed) ----------------
__device__ float g_x[NB * NT * HID];          // 16.4 MB
__device__ float g_qkv[NB * NT * 3 * HID];    // 49 MB   layout (row, 384): Q|K|V
__device__ float g_msg[NB * NT * HID];        // 16.4 MB
__device__ float g_y[NB * NT * HID];          // 16.4 MB
__device__ float g_film[(ESP + 1) * 2 * HID]; // 16.4 MB
__device__ float g_meanea[DE];
__device__ int   g_hist[NN];
__device__ int   g_indptr[NN + 1];
__device__ int   g_cursor[NN];
__device__ int   g_spedge[ESP];
// pre-split weights: 12 matrices (l*4 + {q,k,v,o}); [N=128][K=128] bf16 row-major,
// hi part in g_wA, lo part in g_wB (W^T so B operand is K-major / col-major k x n)
__device__ __nv_bfloat16 g_wA[12 * 128 * 128];
__device__ __nv_bfloat16 g_wB[12 * 128 * 128];

// ---------------- bf16 2-split helper ----------------
__device__ __forceinline__ void split2(float v, unsigned short& h, unsigned short& l) {
    __nv_bfloat16 b1 = __float2bfloat16_rn(v);
    float r = v - __bfloat162float(b1);
    __nv_bfloat16 b2 = __float2bfloat16_rn(r);
    h = __bfloat16_as_ushort(b1);
    l = __bfloat16_as_ushort(b2);
}

// ---------------- CSR build over the 1000 spatial dst nodes ----------------
__global__ void k_zero() {
    int t = blockIdx.x * blockDim.x + threadIdx.x;
    if (t < NN) g_hist[t] = 0;
}

__global__ void k_hist(const int* __restrict__ ei) {
    int j = blockIdx.x * blockDim.x + threadIdx.x;
    if (j < ESP) atomicAdd(&g_hist[ei[ESP + j]], 1);
}

__global__ void k_scan() {   // 1 block, 1024 threads
    __shared__ int sh[1024];
    int t = threadIdx.x;
    int v = (t < NN) ? g_hist[t] : 0;
    sh[t] = v;
    __syncthreads();
    for (int off = 1; off < 1024; off <<= 1) {
        int u = (t >= off) ? sh[t - off] : 0;
        __syncthreads();
        sh[t] += u;
        __syncthreads();
    }
    if (t < NN) { g_indptr[t + 1] = sh[t]; g_cursor[t] = sh[t] - v; }
    if (t == 0) g_indptr[0] = 0;
}

__global__ void k_fill(const int* __restrict__ ei) {
    int j = blockIdx.x * blockDim.x + threadIdx.x;
    if (j < ESP) {
        int d = ei[ESP + j];
        int p = atomicAdd(&g_cursor[d], 1);
        g_spedge[p] = j;
    }
}

// ---------------- mean of spatial edge attrs ----------------
__global__ void k_meanea(const float* __restrict__ ea) {
    __shared__ float sh[256];
    int t = threadIdx.x, c = blockIdx.x;
    float s = 0.f;
    for (int r = t; r < ESP; r += 256) s += ea[r * DE + c];
    sh[t] = s;
    __syncthreads();
    for (int off = 128; off; off >>= 1) {
        if (t < off) sh[t] += sh[t + off];
        __syncthreads();
    }
    if (t == 0) g_meanea[c] = sh[0] / (float)ESP;
}

// ---------------- weight pre-split: 12 blocks, one matrix each ----------------
// input W [K=128][N=128] fp32 row-major -> [N][K] bf16 hi/lo (packed rows of 128)
__global__ void __launch_bounds__(256) k_wsplit(const float* __restrict__ qw,
                                                const float* __restrict__ kw,
                                                const float* __restrict__ vw,
                                                const float* __restrict__ ow) {
    int blk = blockIdx.x;        // l*4 + s
    int l = blk >> 2, s = blk & 3;
    const float* W = (s == 0) ? qw : (s == 1) ? kw : (s == 2) ? vw : ow;
    W += (size_t)l * HID * HID;
    __nv_bfloat16* dA = g_wA + (size_t)blk * 128 * 128;
    __nv_bfloat16* dB = g_wB + (size_t)blk * 128 * 128;
    for (int idx = threadIdx.x; idx < 128 * 128; idx += 256) {
        int n = idx >> 7, k = idx & 127;
        float w = W[k * 128 + n];
        unsigned short h, lo;
        split2(w, h, lo);
        dA[n * 128 + k] = __ushort_as_bfloat16(h);
        dB[n * 128 + k] = __ushort_as_bfloat16(lo);
    }
}

// ---------------- input projection (B*NT, 16) @ (16,128) ----------------
__global__ void __launch_bounds__(128) k_inproj(const float* __restrict__ xw,
                                                const float* __restrict__ w,
                                                const float* __restrict__ b) {
    __shared__ float a[8][FIN];
    int t = threadIdx.x;
    int r0 = blockIdx.x * 8;
    a[t / 16][t % 16] = xw[(size_t)(r0 + t / 16) * FIN + (t % 16)];
    __syncthreads();
    float wk[FIN];
#pragma unroll
    for (int k = 0; k < FIN; k++) wk[k] = w[k * HID + t];
    float bb = b[t];
#pragma unroll
    for (int rr = 0; rr < 8; rr++) {
        float s = bb;
#pragma unroll
        for (int k = 0; k < FIN; k++) s += a[rr][k] * wk[k];
        g_x[(size_t)(r0 + rr) * HID + t] = s;
    }
}

// ---------------- FiLM: (16001, 8) @ (8, 256) ----------------
__global__ void __launch_bounds__(256) k_film(const float* __restrict__ ea,
                                              const float* __restrict__ fw,
                                              const float* __restrict__ fb) {
    __shared__ float at[DE];
    int j = blockIdx.x, c = threadIdx.x;
    if (c < DE) at[c] = (j < ESP) ? ea[j * DE + c] : g_meanea[c];
    __syncthreads();
    float s = fb[c];
#pragma unroll
    for (int k = 0; k < DE; k++) s += at[k] * fw[k * 256 + c];
    g_film[(size_t)j * 256 + c] = s;
}

// ================= mma.sync bf16-split-2 GEMM =================
// C[M,128] = A[M,128] @ W[128,128] + bias via D = A1B1 + A1B2 + A2B1,
// bf16 operands, fp32 accumulators (mma.sync.m16n8k16.row.col, HMMA fallback path).
// CTA = 128x128 tile, 8 warps (4 M x 2 N), each warp 32x64.
// grid (250, nz): mode 0 -> A=g_x,  C=g_qkv (ldc 384, cOff=z*128), mat = matBase+z
//                 mode 1 -> A=g_msg,C=g_y   (ldc 128, cOff=0),     mat = matBase
#define KP 136                         // padded row stride (bf16 elems): conflict-free frags
#define TILE_B (128 * KP * 2)          // 34816 bytes per tile
#define OFF_A1 0
#define OFF_A2 (TILE_B)
#define OFF_B1 (2 * TILE_B)
#define OFF_B2 (3 * TILE_B)
#define OFF_BIAS (4 * TILE_B)
#define SMEM_MMA (OFF_BIAS + 512)      // 139776 bytes

#define MMA16816(D, A0, A1_, A2_, A3_, B0, B1_)                                  \
    asm volatile(                                                                \
        "mma.sync.aligned.m16n8k16.row.col.f32.bf16.bf16.f32 "                   \
        "{%0,%1,%2,%3}, {%4,%5,%6,%7}, {%8,%9}, {%0,%1,%2,%3};"                  \
        : "+f"(D[0]), "+f"(D[1]), "+f"(D[2]), "+f"(D[3])                         \
        : "r"(A0), "r"(A1_), "r"(A2_), "r"(A3_), "r"(B0), "r"(B1_))

__global__ void __launch_bounds__(256, 1)
k_gemm_mma(int mode, int matBase,
           const float* __restrict__ bq, const float* __restrict__ bk,
           const float* __restrict__ bv, int ldc) {
    extern __shared__ char smem[];
    __nv_bfloat16* sA1 = (__nv_bfloat16*)(smem + OFF_A1);
    __nv_bfloat16* sA2 = (__nv_bfloat16*)(smem + OFF_A2);
    __nv_bfloat16* sB1 = (__nv_bfloat16*)(smem + OFF_B1);
    __nv_bfloat16* sB2 = (__nv_bfloat16*)(smem + OFF_B2);
    float* sbias = (float*)(smem + OFF_BIAS);

    int tid = threadIdx.x;
    int z = blockIdx.y;
    int r0 = blockIdx.x * 128;
    int mat = matBase + z;
    int cOff = z * HID;
    const float* __restrict__ A = (mode == 0) ? g_x : g_msg;
    float* __restrict__ C = (mode == 0) ? g_qkv : g_y;
    const float* __restrict__ bias = (z == 0) ? bq : (z == 1) ? bk : bv;

    if (tid < 128) sbias[tid] = bias[tid];

    // ---- A tile: load fp32, split to bf16 hi/lo, store padded ----
    for (int idx = tid; idx < 4096; idx += 256) {          // 4096 float4 groups
        int row = idx >> 5, k4 = (idx & 31) << 2;
        float4 a = *(const float4*)(A + (size_t)(r0 + row) * 128 + k4);
        unsigned short h0, l0, h1, l1, h2, l2, h3, l3;
        split2(a.x, h0, l0); split2(a.y, h1, l1);
        split2(a.z, h2, l2); split2(a.w, h3, l3);
        uint2 hv = make_uint2((uint32_t)h0 | ((uint32_t)h1 << 16),
                              (uint32_t)h2 | ((uint32_t)h3 << 16));
        uint2 lv = make_uint2((uint32_t)l0 | ((uint32_t)l1 << 16),
                              (uint32_t)l2 | ((uint32_t)l3 << 16));
        *(uint2*)(sA1 + row * KP + k4) = hv;
        *(uint2*)(sA2 + row * KP + k4) = lv;
    }
    // ---- B tiles: copy pre-split [N][K] images into padded smem ----
    {
        const uint4* srcA = (const uint4*)(g_wA + (size_t)mat * 128 * 128);
        const uint4* srcB = (const uint4*)(g_wB + (size_t)mat * 128 * 128);
        for (int i = tid; i < 2048; i += 256) {            // 16 uint4 per 128-elem row
            int row = i >> 4, q = i & 15;
            ((uint4*)(sB1 + row * KP))[q] = srcA[i];
            ((uint4*)(sB2 + row * KP))[q] = srcB[i];
        }
    }
    __syncthreads();

    int wid = tid >> 5, lane = tid & 31;
    int warpM = wid & 3, warpN = wid >> 2;                 // 4 x 2 warp grid
    int g = lane >> 2, tg = lane & 3;
    int mrow0 = warpM * 32;
    int ncol0 = warpN * 64;

    float acc[2][8][4];
#pragma unroll
    for (int m = 0; m < 2; m++)
#pragma unroll
        for (int nf = 0; nf < 8; nf++)
#pragma unroll
            for (int j = 0; j < 4; j++) acc[m][nf][j] = 0.f;

#pragma unroll
    for (int pass = 0; pass < 3; pass++) {
        const __nv_bfloat16* As = (pass < 2) ? sA1 : sA2;
        const __nv_bfloat16* Bs = (pass == 1) ? sB2 : sB1;
#pragma unroll
        for (int k0 = 0; k0 < 128; k0 += 16) {
            uint32_t afr[2][4];
#pragma unroll
            for (int m = 0; m < 2; m++) {
                const __nv_bfloat16* ab = As + (mrow0 + m * 16 + g) * KP + k0 + tg * 2;
                afr[m][0] = *(const uint32_t*)(ab);
                afr[m][1] = *(const uint32_t*)(ab + 8 * KP);
                afr[m][2] = *(const uint32_t*)(ab + 8);
                afr[m][3] = *(const uint32_t*)(ab + 8 * KP + 8);
            }
#pragma unroll
            for (int nf = 0; nf < 8; nf++) {
                const __nv_bfloat16* bb = Bs + (ncol0 + nf * 8 + g) * KP + k0 + tg * 2;
                uint32_t b0r = *(const uint32_t*)(bb);
                uint32_t b1r = *(const uint32_t*)(bb + 8);
                MMA16816(acc[0][nf], afr[0][0], afr[0][1], afr[0][2], afr[0][3], b0r, b1r);
                MMA16816(acc[1][nf], afr[1][0], afr[1][1], afr[1][2], afr[1][3], b0r, b1r);
            }
        }
    }

    // ---- epilogue: D frag layout c0=D[g][tg*2], c1=D[g][tg*2+1], c2/c3 at row+8 ----
#pragma unroll
    for (int m = 0; m < 2; m++) {
        int r = r0 + mrow0 + m * 16 + g;
#pragma unroll
        for (int nf = 0; nf < 8; nf++) {
            int c = ncol0 + nf * 8 + tg * 2;
            float2 v0 = make_float2(acc[m][nf][0] + sbias[c], acc[m][nf][1] + sbias[c + 1]);
            float2 v1 = make_float2(acc[m][nf][2] + sbias[c], acc[m][nf][3] + sbias[c + 1]);
            *(float2*)(C + (size_t)r * ldc + cOff + c) = v0;
            *(float2*)(C + (size_t)(r + 8) * ldc + cOff + c) = v1;
        }
    }
}

// ---------------- graph attention: warp per (batch, node), online softmax ----------------
__global__ void __launch_bounds__(256) k_attn(const int* __restrict__ ei) {
    int gwarp = (blockIdx.x * blockDim.x + threadIdx.x) >> 5;
    if (gwarp >= NB * NT) return;
    int lane = threadIdx.x & 31;
    int b = gwarp / NT, n = gwarp - b * NT;
    int w = n / NN, d = n - w * NN;

    const float* qrow = g_qkv + ((size_t)(b * NT + n)) * 384;
    float4 q = *(const float4*)(qrow + lane * 4);

    float m = -INFINITY, s = 0.f;
    float4 acc = make_float4(0.f, 0.f, 0.f, 0.f);

    int beg = g_indptr[d], end = g_indptr[d + 1];
    int nsp = end - beg;
    int nEdges = nsp + (w > 0 ? 1 : 0);

    for (int i = 0; i < nEdges; i++) {
        int src, fidx;
        if (i < nsp) {
            int j = g_spedge[beg + i];
            src = ei[j] + w * NN;
            fidx = j;
        } else {
            src = n - NN;
            fidx = ESP;
        }
        const float* krow = g_qkv + ((size_t)(b * NT + src)) * 384 + 128;
        float4 k = *(const float4*)(krow + lane * 4);
        float4 v = *(const float4*)(krow + 128 + lane * 4);
        const float* f = g_film + (size_t)fidx * 256 + lane * 4;
        float4 ga = *(const float4*)f;
        float4 be = *(const float4*)(f + 128);

        float p = q.x * (k.x * (1.f + ga.x) + be.x)
                + q.y * (k.y * (1.f + ga.y) + be.y)
                + q.z * (k.z * (1.f + ga.z) + be.z)
                + q.w * (k.w * (1.f + ga.w) + be.w);
        p += __shfl_xor_sync(0xffffffffu, p, 4);
        p += __shfl_xor_sync(0xffffffffu, p, 2);
        p += __shfl_xor_sync(0xffffffffu, p, 1);
        float logit = p * 0.1767766952966369f;  // 1/sqrt(32)

        float mn = fmaxf(m, logit);
        float sc = __expf(m - mn);
        float wt = __expf(logit - mn);
        s = s * sc + wt;
        acc.x = acc.x * sc + wt * v.x;
        acc.y = acc.y * sc + wt * v.y;
        acc.z = acc.z * sc + wt * v.z;
        acc.w = acc.w * sc + wt * v.w;
        m = mn;
    }
    float inv = 1.f / (s + 1e-16f);
    float4 o = make_float4(acc.x * inv, acc.y * inv, acc.z * inv, acc.w * inv);
    *(float4*)(g_msg + ((size_t)(b * NT + n)) * HID + lane * 4) = o;
}

// ---------------- residual + layernorm, in-place on g_x ----------------
__global__ void __launch_bounds__(128) k_ln(const float* __restrict__ gamma,
                                            const float* __restrict__ beta) {
    int row = blockIdx.x, t = threadIdx.x;
    size_t idx = (size_t)row * HID + t;
    float v = g_x[idx] + g_y[idx];
    float a = v, q = v * v;
#pragma unroll
    for (int off = 16; off; off >>= 1) {
        a += __shfl_xor_sync(0xffffffffu, a, off);
        q += __shfl_xor_sync(0xffffffffu, q, off);
    }
    __shared__ float s1[4], s2[4];
    int wid = t >> 5;
    if ((t & 31) == 0) { s1[wid] = a; s2[wid] = q; }
    __syncthreads();
    float ta = s1[0] + s1[1] + s1[2] + s1[3];
    float tq = s2[0] + s2[1] + s2[2] + s2[3];
    float mu = ta * (1.f / HID);
    float var = tq * (1.f / HID) - mu * mu;
    g_x[idx] = (v - mu) * rsqrtf(var + 1e-5f) * gamma[t] + beta[t];
}

// ---------------- head ----------------
__global__ void __launch_bounds__(128) k_head(const float* __restrict__ hw,
                                              const float* __restrict__ hb,
                                              float* __restrict__ out) {
    int gwarp = (blockIdx.x * blockDim.x + threadIdx.x) >> 5;
    if (gwarp >= NB * NN) return;
    int lane = threadIdx.x & 31;
    int b = gwarp / NN, n = gwarp - b * NN;
    const float* xr = g_x + ((size_t)(b * NT + (NW - 1) * NN + n)) * HID;
    float4 xv = *(const float4*)(xr + lane * 4);
    float4 wv = *(const float4*)(hw + lane * 4);
    float p = xv.x * wv.x + xv.y * wv.y + xv.z * wv.z + xv.w * wv.w;
#pragma unroll
    for (int off = 16; off; off >>= 1) p += __shfl_xor_sync(0xffffffffu, p, off);
    if (lane == 0) {
        float z = p + hb[0];
        out[gwarp] = fmaxf(z, 0.f) + log1pf(__expf(-fabsf(z)));
    }
}

// ---------------- launch ----------------
extern "C" void kernel_launch(void* const* d_in, const int* in_sizes, int n_in,
                              void* d_out, int out_size) {
    const float* xw  = (const float*)d_in[0];
    const int*   ei  = (const int*)d_in[1];
    const float* ea  = (const float*)d_in[2];
    const float* inw = (const float*)d_in[3];
    const float* inb = (const float*)d_in[4];
    const float* qw  = (const float*)d_in[5];
    const float* qb  = (const float*)d_in[6];
    const float* kw  = (const float*)d_in[7];
    const float* kb  = (const float*)d_in[8];
    const float* vw  = (const float*)d_in[9];
    const float* vb  = (const float*)d_in[10];
    const float* fw  = (const float*)d_in[11];
    const float* fb  = (const float*)d_in[12];
    const float* ow  = (const float*)d_in[13];
    const float* ob  = (const float*)d_in[14];
    const float* lng = (const float*)d_in[15];
    const float* lnb = (const float*)d_in[16];
    const float* hw  = (const float*)d_in[17];
    const float* hb  = (const float*)d_in[18];
    float* out = (float*)d_out;

    cudaFuncSetAttribute(k_gemm_mma, cudaFuncAttributeMaxDynamicSharedMemorySize,
                         SMEM_MMA);

    // CSR over spatial dst + mean edge attr + weight pre-split
    k_zero<<<(NN + 255) / 256, 256>>>();
    k_hist<<<(ESP + 255) / 256, 256>>>(ei);
    k_scan<<<1, 1024>>>();
    k_fill<<<(ESP + 255) / 256, 256>>>(ei);
    k_meanea<<<DE, 256>>>(ea);
    k_wsplit<<<12, 256>>>(qw, kw, vw, ow);

    // input projection
    k_inproj<<<(NB * NT) / 8, 128>>>(xw, inw, inb);

    const int M = NB * NT;  // 32000
    dim3 gQKV(M / 128, 3);
    dim3 gO(M / 128, 1);

    for (int l = 0; l < NLAYER; l++) {
        k_film<<<ESP + 1, 256>>>(ea, fw + (size_t)l * DE * 256, fb + (size_t)l * 256);
        k_gemm_mma<<<gQKV, 256, SMEM_MMA>>>(0, l * 4,
                                            qb + l * HID, kb + l * HID, vb + l * HID,
                                            384);
        k_attn<<<(NB * NT) / 8, 256>>>(ei);
        k_gemm_mma<<<gO, 256, SMEM_MMA>>>(1, l * 4 + 3,
                                          ob + l * HID, ob, ob, 128);
        k_ln<<<M, 128>>>(lng + l * HID, lnb + l * HID);
    }

    k_head<<<(NB * NN + 3) / 4, 128>>>(hw, hb, out);
}